// round 16
// baseline (speedup 1.0000x reference)
#include <cuda_runtime.h>
#include <cuda_fp16.h>
#include <math.h>
#include <stdint.h>

#define EMBED   1024
#define RANK    8
#define HEADS   16
#define HDIM    64
#define NBATCH  2
#define SEQ     2048
#define TOKENS  (NBATCH*SEQ)
#define LORA_SCALE 2.0f
#define LOG2E   1.44269504088896f

// ---------------- scratch (fp16 pairs stored as uint32) ----------------
__device__ uint32_t g_Weff[4][EMBED*EMBED/2];
__device__ uint32_t g_xt[TOKENS*EMBED/2];
__device__ uint32_t g_Q[TOKENS*EMBED/2];
__device__ uint32_t g_K[TOKENS*EMBED/2];
__device__ uint32_t g_V[TOKENS*EMBED/2];
__device__ uint32_t g_attn[TOKENS*EMBED/2];

// ---------------- helpers ----------------
__device__ __forceinline__ uint32_t pkh2(float a, float b) {
    __half2 h = __floats2half2_rn(a, b);
    return *(uint32_t*)&h;
}
__device__ __forceinline__ uint32_t pexp2(float a, float b, __half2 m2) {
    __half2 v = __hsub2(__floats2half2_rn(a, b), m2);
    __half2 e = h2exp2(v);
    return *(uint32_t*)&e;
}
__device__ __forceinline__ void mma_f16(float c[4], const uint32_t a[4], const uint32_t b[2]) {
    asm volatile("mma.sync.aligned.m16n8k16.row.col.f32.f16.f16.f32 "
        "{%0,%1,%2,%3}, {%4,%5,%6,%7}, {%8,%9}, {%0,%1,%2,%3};"
        : "+f"(c[0]), "+f"(c[1]), "+f"(c[2]), "+f"(c[3])
        : "r"(a[0]), "r"(a[1]), "r"(a[2]), "r"(a[3]), "r"(b[0]), "r"(b[1]));
}
__device__ __forceinline__ void ldsm4(uint32_t r[4], uint32_t addr) {
    asm volatile("ldmatrix.sync.aligned.m8n8.x4.shared.b16 {%0,%1,%2,%3}, [%4];"
        : "=r"(r[0]), "=r"(r[1]), "=r"(r[2]), "=r"(r[3]) : "r"(addr));
}
__device__ __forceinline__ void ldsm4t(uint32_t r[4], uint32_t addr) {
    asm volatile("ldmatrix.sync.aligned.m8n8.x4.trans.shared.b16 {%0,%1,%2,%3}, [%4];"
        : "=r"(r[0]), "=r"(r[1]), "=r"(r[2]), "=r"(r[3]) : "r"(addr));
}
__device__ __forceinline__ void cp16(uint32_t saddr, const void* gaddr) {
    asm volatile("cp.async.cg.shared.global [%0], [%1], 16;" :: "r"(saddr), "l"(gaddr));
}
#define CP_COMMIT() asm volatile("cp.async.commit_group;")
template<int N> __device__ __forceinline__ void cp_wait() {
    asm volatile("cp.async.wait_group %0;" :: "n"(N));
}

// ---------------- xconv: fp32 -> fp16 ----------------
__global__ void xconv(const float4* __restrict__ in, uint2* __restrict__ out) {
    int i = blockIdx.x * blockDim.x + threadIdx.x;
    float4 v = in[i];
    out[i] = make_uint2(pkh2(v.x, v.y), pkh2(v.z, v.w));
}

// ---------------- fold: Weff[z] = h(wscale * (W + 2 * B @ A)), vectorized ----------------
__global__ void fold4_kernel(const float* __restrict__ W0, const float* __restrict__ A0, const float* __restrict__ B0,
                             const float* __restrict__ W1, const float* __restrict__ A1, const float* __restrict__ B1,
                             const float* __restrict__ W2, const float* __restrict__ A2, const float* __restrict__ B2,
                             const float* __restrict__ W3, const float* __restrict__ A3, const float* __restrict__ B3) {
    int z = blockIdx.y;
    const float *W, *A, *B;
    if (z == 0) { W = W0; A = A0; B = B0; }
    else if (z == 1) { W = W1; A = A1; B = B1; }
    else if (z == 2) { W = W2; A = A2; B = B2; }
    else { W = W3; A = A3; B = B3; }
    float wscale = (z == 0) ? 0.125f * LOG2E : 1.0f;
    uint32_t* out = g_Weff[z];
    int idx = blockIdx.x * blockDim.x + threadIdx.x;   // quad index
    int o = idx >> 8;                                  // row (1024 cols / 4 = 256 quads)
    int i = (idx & 255) * 4;
    float4 w = *(const float4*)(W + o*EMBED + i);
    float s0 = 0.f, s1 = 0.f, s2 = 0.f, s3 = 0.f;
#pragma unroll
    for (int r = 0; r < RANK; r++) {
        float br = B[o*RANK + r];
        float4 a = *(const float4*)(A + r*EMBED + i);
        s0 = fmaf(br, a.x, s0); s1 = fmaf(br, a.y, s1);
        s2 = fmaf(br, a.z, s2); s3 = fmaf(br, a.w, s3);
    }
    uint2 u;
    u.x = pkh2(wscale * (w.x + LORA_SCALE * s0), wscale * (w.y + LORA_SCALE * s1));
    u.y = pkh2(wscale * (w.z + LORA_SCALE * s2), wscale * (w.w + LORA_SCALE * s3));
    *(uint2*)(out + idx*2) = u;
}

// ---------------- fp16 GEMM: C[M,N] = A[M,K] @ Bw[N,K]^T + bias ----------------
// CTA 128x128, 256 threads (8 warps, warp tile 32x64), k64 stages, 2-slot ring.
// 144B rows (attn-proven), 1 barrier per k64. smem 73728 -> 2 CTAs/SM.
// Halved weight traffic vs 64-row tiles (qkv was ~70% LTS-bound).
#define GAST 18432           // A stage bytes (128 rows * 144B)
#define GSTAGE 36864         // A + B
#define GEMM_SMEM (2*GSTAGE) // 73728
template<int MODE>
__global__ __launch_bounds__(256, 2)
void gemm_tc(const __half* __restrict__ A, const __half* __restrict__ Wbase,
             const float* __restrict__ bz0, const float* __restrict__ bz1, const float* __restrict__ bz2,
             uint32_t* __restrict__ o0, uint32_t* __restrict__ o1, uint32_t* __restrict__ o2,
             float* __restrict__ ofp) {
    extern __shared__ char smg[];
    const int z = (MODE == 0) ? blockIdx.z : 0;
    const __half* Bw = Wbase + (size_t)z * (EMBED*EMBED);
    const float* bias = (z == 0) ? bz0 : (z == 1) ? bz1 : bz2;
    const float bscale = (MODE == 0 && z == 0) ? 0.125f * LOG2E : 1.0f;
    uint32_t* Ch = (z == 0) ? o0 : (z == 1) ? o1 : o2;

    const int tid = threadIdx.x, warp = tid >> 5, lane = tid & 31;
    const int g = lane >> 2, c = lane & 3;
    const int wm = (warp & 3) * 32, wn = (warp >> 2) * 64;
    const int m0 = blockIdx.y * 128, n0 = blockIdx.x * 128;

    const uint32_t sbase = (uint32_t)__cvta_generic_to_shared(smg);

    auto issue = [&](int s) {
        uint32_t off = sbase + (uint32_t)(s & 1) * GSTAGE;
        // A: 128 rows x 8 chunks = 1024 cp16 (4 per thread)
#pragma unroll
        for (int p = 0; p < 4; p++) {
            int idx = tid + 256*p;
            int row = idx >> 3, part = idx & 7;
            cp16(off + row*144 + part*16,
                 A + (size_t)(m0 + row)*EMBED + s*64 + part*8);
        }
        // B: 128 rows x 8 chunks = 1024 cp16 (4 per thread)
#pragma unroll
        for (int p = 0; p < 4; p++) {
            int idx = tid + 256*p;
            int row = idx >> 3, part = idx & 7;
            cp16(off + GAST + row*144 + part*16,
                 Bw + (size_t)(n0 + row)*EMBED + s*64 + part*8);
        }
    };

    float acc[2][8][4];
#pragma unroll
    for (int t = 0; t < 2; t++)
#pragma unroll
        for (int j = 0; j < 8; j++)
#pragma unroll
            for (int r = 0; r < 4; r++) acc[t][j][r] = 0.f;

    const int a_row  = lane & 15;
    const int a_half = (lane >> 4) * 16;
    const int b_row  = (lane & 7) + ((lane >> 4) << 3);
    const int b_half = ((lane >> 3) & 1) * 16;

    issue(0); CP_COMMIT();
    cp_wait<0>(); __syncthreads();

    for (int s = 0; s < EMBED/64; s++) {   // 16 iterations
        if (s + 1 < EMBED/64) { issue(s + 1); CP_COMMIT(); }

        uint32_t offA = sbase + (uint32_t)(s & 1) * GSTAGE;
        uint32_t offB = offA + GAST;

#pragma unroll
        for (int kk = 0; kk < 4; kk++) {
            uint32_t af[2][4], bf[8][2];
#pragma unroll
            for (int t = 0; t < 2; t++)
                ldsm4(af[t], offA + (uint32_t)(wm + 16*t + a_row)*144 + a_half + kk*32);
#pragma unroll
            for (int jj = 0; jj < 4; jj++) {
                uint32_t r[4];
                ldsm4(r, offB + (uint32_t)(wn + 16*jj + b_row)*144 + b_half + kk*32);
                bf[2*jj][0] = r[0]; bf[2*jj][1] = r[1];
                bf[2*jj+1][0] = r[2]; bf[2*jj+1][1] = r[3];
            }
#pragma unroll
            for (int t = 0; t < 2; t++)
#pragma unroll
                for (int j = 0; j < 8; j++)
                    mma_f16(acc[t][j], af[t], bf[j]);
        }

        cp_wait<0>();
        __syncthreads();
    }

    // epilogue
#pragma unroll
    for (int j = 0; j < 8; j++) {
        int col = n0 + wn + 8*j + 2*c;
        float bv0 = bias[col] * bscale, bv1 = bias[col + 1] * bscale;
#pragma unroll
        for (int t = 0; t < 2; t++) {
            int row0 = m0 + wm + 16*t + g;
            float v00 = acc[t][j][0] + bv0, v01 = acc[t][j][1] + bv1;
            float v10 = acc[t][j][2] + bv0, v11 = acc[t][j][3] + bv1;
            if (MODE == 1) {
                *(float2*)(ofp + (size_t)row0*EMBED + col)     = make_float2(v00, v01);
                *(float2*)(ofp + (size_t)(row0+8)*EMBED + col) = make_float2(v10, v11);
            } else {
                Ch[((size_t)row0*EMBED + col) >> 1]     = pkh2(v00, v01);
                Ch[((size_t)(row0+8)*EMBED + col) >> 1] = pkh2(v10, v11);
            }
        }
    }
}

// ---------------- flash attention: round-10 config (frozen) ----------------
#define KOB(s)  ((uint32_t)(s)*9216u)
#define VOB(s)  (18432u + (uint32_t)(s)*9216u)
#define QO      36864u
#define ATTN_SMEM (36864 + 9216)   // 46080
#define NT (SEQ/64)

__global__ __launch_bounds__(128, 4)
void attn_tc(const __half* __restrict__ Qg, const __half* __restrict__ Kg,
             const __half* __restrict__ Vg, uint32_t* __restrict__ Og) {
    extern __shared__ char sma[];
    const uint32_t sbase = (uint32_t)__cvta_generic_to_shared(sma);

    const int qt = blockIdx.x, h = blockIdx.y, nb = blockIdx.z;
    const int tid = threadIdx.x, warp = tid >> 5, lane = tid & 31;
    const int g = lane >> 2, c = lane & 3;
    const int q0 = warp * 16;
    const int base_q = nb*SEQ + qt*64;
    const int col0 = h * HDIM;

    auto kvissue = [&](int kt) {
        int s = kt & 1;
        int base_k = nb*SEQ + kt*64;
#pragma unroll
        for (int p = 0; p < 4; p++) {
            int idx = tid + 128*p;
            int row = idx >> 3, q = idx & 7;
            cp16(sbase + KOB(s) + row*144 + q*16,
                 Kg + (size_t)(base_k + row)*EMBED + col0 + 8*q);
        }
#pragma unroll
        for (int p = 0; p < 4; p++) {
            int idx = tid + 128*p;
            int row = idx >> 3, q = idx & 7;
            cp16(sbase + VOB(s) + row*144 + q*16,
                 Vg + (size_t)(base_k + row)*EMBED + col0 + 8*q);
        }
    };

#pragma unroll
    for (int p = 0; p < 4; p++) {
        int idx = tid + 128*p;
        int row = idx >> 3, q = idx & 7;
        cp16(sbase + QO + row*144 + q*16,
             Qg + (size_t)(base_q + row)*EMBED + col0 + 8*q);
    }
    CP_COMMIT();
    kvissue(0); CP_COMMIT();

    const int b_row  = (lane & 7) + ((lane >> 4) << 3);
    const int b_half = ((lane >> 3) & 1) * 16;
    const int v_row  = (lane & 7) + (((lane >> 3) & 1) << 3);
    const int v_half = (lane >> 4) * 16;

    cp_wait<0>(); __syncthreads();
    uint32_t qf[4][4];
#pragma unroll
    for (int kk = 0; kk < 4; kk++)
        ldsm4(qf[kk], sbase + QO + (uint32_t)(q0 + (lane & 15))*144 + (lane >> 4)*16 + kk*32);

    float of[8][4], of_l[4];
#pragma unroll
    for (int j = 0; j < 8; j++)
#pragma unroll
        for (int r = 0; r < 4; r++) of[j][r] = 0.f;
#pragma unroll
    for (int r = 0; r < 4; r++) of_l[r] = 0.f;
    float m_lo = -1e30f, m_hi = -1e30f;
    const uint32_t ones2 = 0x3C003C00u;

    for (int kt = 0; kt < NT; kt++) {
        if (kt + 1 < NT) { kvissue(kt + 1); CP_COMMIT(); }
        const uint32_t Ko = KOB(kt & 1);
        const uint32_t Vo = VOB(kt & 1);

        float sf[8][4];
#pragma unroll
        for (int j = 0; j < 8; j++)
#pragma unroll
            for (int r = 0; r < 4; r++) sf[j][r] = 0.f;
#pragma unroll
        for (int kk = 0; kk < 4; kk++) {
            uint32_t bf[8][2];
#pragma unroll
            for (int jj = 0; jj < 4; jj++) {
                uint32_t r[4];
                ldsm4(r, sbase + Ko + (uint32_t)(16*jj + b_row)*144 + b_half + kk*32);
                bf[2*jj][0] = r[0]; bf[2*jj][1] = r[1];
                bf[2*jj+1][0] = r[2]; bf[2*jj+1][1] = r[3];
            }
#pragma unroll
            for (int j = 0; j < 8; j++)
                mma_f16(sf[j], qf[kk], bf[j]);
        }

        float mx_lo = -1e30f, mx_hi = -1e30f;
#pragma unroll
        for (int j = 0; j < 8; j++) {
            mx_lo = fmaxf(mx_lo, fmaxf(sf[j][0], sf[j][1]));
            mx_hi = fmaxf(mx_hi, fmaxf(sf[j][2], sf[j][3]));
        }
        mx_lo = fmaxf(mx_lo, __shfl_xor_sync(0xffffffffu, mx_lo, 1));
        mx_lo = fmaxf(mx_lo, __shfl_xor_sync(0xffffffffu, mx_lo, 2));
        mx_hi = fmaxf(mx_hi, __shfl_xor_sync(0xffffffffu, mx_hi, 1));
        mx_hi = fmaxf(mx_hi, __shfl_xor_sync(0xffffffffu, mx_hi, 2));

        bool need_rescale = (mx_lo > m_lo) || (mx_hi > m_hi);
        float mn_lo = fmaxf(m_lo, mx_lo);
        float mn_hi = fmaxf(m_hi, mx_hi);

        if (need_rescale) {
            float alpha_lo = exp2f(m_lo - mn_lo);
            float alpha_hi = exp2f(m_hi - mn_hi);
#pragma unroll
            for (int j = 0; j < 8; j++) {
                of[j][0] *= alpha_lo; of[j][1] *= alpha_lo;
                of[j][2] *= alpha_hi; of[j][3] *= alpha_hi;
            }
            of_l[0] *= alpha_lo; of_l[1] *= alpha_lo;
            of_l[2] *= alpha_hi; of_l[3] *= alpha_hi;
            m_lo = mn_lo; m_hi = mn_hi;
        }

        __half2 ml2 = __float2half2_rn(mn_lo);
        __half2 mh2 = __float2half2_rn(mn_hi);
        uint32_t pa[4][4];
#pragma unroll
        for (int kk = 0; kk < 4; kk++) {
            pa[kk][0] = pexp2(sf[2*kk][0],   sf[2*kk][1],   ml2);
            pa[kk][1] = pexp2(sf[2*kk][2],   sf[2*kk][3],   mh2);
            pa[kk][2] = pexp2(sf[2*kk+1][0], sf[2*kk+1][1], ml2);
            pa[kk][3] = pexp2(sf[2*kk+1][2], sf[2*kk+1][3], mh2);
        }

#pragma unroll
        for (int kk = 0; kk < 4; kk++) {
#pragma unroll
            for (int dd = 0; dd < 4; dd++) {
                uint32_t r[4];
                ldsm4t(r, sbase + Vo + (uint32_t)(kk*16 + v_row)*144 + dd*32 + v_half);
                uint32_t b0[2] = { r[0], r[1] };
                uint32_t b1[2] = { r[2], r[3] };
                mma_f16(of[2*dd],   pa[kk], b0);
                mma_f16(of[2*dd+1], pa[kk], b1);
            }
            uint32_t ob[2] = { ones2, ones2 };
            mma_f16(of_l, pa[kk], ob);
        }

        cp_wait<0>();
        __syncthreads();
    }

    float il_lo = 1.f / of_l[0], il_hi = 1.f / of_l[2];
#pragma unroll
    for (int dj = 0; dj < 8; dj++) {
        int col = col0 + 8*dj + 2*c;
        Og[((size_t)(base_q + q0 + g)*EMBED + col) >> 1]     = pkh2(of[dj][0]*il_lo, of[dj][1]*il_lo);
        Og[((size_t)(base_q + q0 + g + 8)*EMBED + col) >> 1] = pkh2(of[dj][2]*il_hi, of[dj][3]*il_hi);
    }
}

// ---------------- launch ----------------
extern "C" void kernel_launch(void* const* d_in, const int* in_sizes, int n_in,
                              void* d_out, int out_size) {
    const float* x  = (const float*)d_in[0];
    const float* Wq = (const float*)d_in[1];
    const float* bq = (const float*)d_in[2];
    const float* Aq = (const float*)d_in[3];
    const float* Bq = (const float*)d_in[4];
    const float* Wk = (const float*)d_in[5];
    const float* bk = (const float*)d_in[6];
    const float* Ak = (const float*)d_in[7];
    const float* Bk = (const float*)d_in[8];
    const float* Wv = (const float*)d_in[9];
    const float* bv = (const float*)d_in[10];
    const float* Av = (const float*)d_in[11];
    const float* Bv = (const float*)d_in[12];
    const float* Wo = (const float*)d_in[13];
    const float* bo = (const float*)d_in[14];
    const float* Ao = (const float*)d_in[15];
    const float* Bo = (const float*)d_in[16];
    float* out = (float*)d_out;

    uint32_t *Weff, *xt, *Q, *K, *V, *attn;
    cudaGetSymbolAddress((void**)&Weff, g_Weff);
    cudaGetSymbolAddress((void**)&xt, g_xt);
    cudaGetSymbolAddress((void**)&Q, g_Q);
    cudaGetSymbolAddress((void**)&K, g_K);
    cudaGetSymbolAddress((void**)&V, g_V);
    cudaGetSymbolAddress((void**)&attn, g_attn);

    // 0) x -> fp16
    xconv<<<TOKENS*EMBED/4/256, 256>>>((const float4*)x, (uint2*)xt);

    // 1) fold LoRA into effective fp16 weights (vectorized; Q pre-scaled)
    dim3 fgrid(EMBED*EMBED/4/256, 4);
    fold4_kernel<<<fgrid, 256>>>(Wq, Aq, Bq, Wk, Ak, Bk, Wv, Av, Bv, Wo, Ao, Bo);

    // 2) fused Q/K/V projections (128x128 tiles, k64 stages, 2 CTAs/SM)
    cudaFuncSetAttribute(gemm_tc<0>, cudaFuncAttributeMaxDynamicSharedMemorySize, GEMM_SMEM);
    cudaFuncSetAttribute(gemm_tc<1>, cudaFuncAttributeMaxDynamicSharedMemorySize, GEMM_SMEM);
    dim3 qkv_grid(EMBED/128, TOKENS/128, 3);
    gemm_tc<0><<<qkv_grid, 256, GEMM_SMEM>>>((const __half*)xt, (const __half*)Weff,
                                             bq, bk, bv, Q, K, V, nullptr);

    // 3) attention (frozen round-10 config)
    dim3 agrid(SEQ/64, HEADS, NBATCH);
    attn_tc<<<agrid, 128, ATTN_SMEM>>>((const __half*)Q, (const __half*)K, (const __half*)V, attn);

    // 4) output projection (fp32 out + bias; 256 CTAs = single wave)
    dim3 ogrid(EMBED/128, TOKENS/128, 1);
    gemm_tc<1><<<ogrid, 256, GEMM_SMEM>>>((const __half*)attn,
                                          (const __half*)(Weff + 3*(size_t)(EMBED*EMBED/2)),
                                          bo, bo, bo, nullptr, nullptr, nullptr, out);
}

// round 17
// speedup vs baseline: 1.0490x; 1.0490x over previous
#include <cuda_runtime.h>
#include <cuda_fp16.h>
#include <math.h>
#include <stdint.h>

#define EMBED   1024
#define RANK    8
#define HEADS   16
#define HDIM    64
#define NBATCH  2
#define SEQ     2048
#define TOKENS  (NBATCH*SEQ)
#define LORA_SCALE 2.0f
#define LOG2E   1.44269504088896f

// ---------------- scratch (fp16 pairs stored as uint32) ----------------
__device__ uint32_t g_Weff[4][EMBED*EMBED/2];
__device__ uint32_t g_xt[TOKENS*EMBED/2];
__device__ uint32_t g_Q[TOKENS*EMBED/2];
__device__ uint32_t g_K[TOKENS*EMBED/2];
__device__ uint32_t g_V[TOKENS*EMBED/2];
__device__ uint32_t g_attn[TOKENS*EMBED/2];

// ---------------- helpers ----------------
__device__ __forceinline__ uint32_t pkh2(float a, float b) {
    __half2 h = __floats2half2_rn(a, b);
    return *(uint32_t*)&h;
}
__device__ __forceinline__ uint32_t pexp2(float a, float b, __half2 m2) {
    __half2 v = __hsub2(__floats2half2_rn(a, b), m2);
    __half2 e = h2exp2(v);
    return *(uint32_t*)&e;
}
__device__ __forceinline__ void mma_f16(float c[4], const uint32_t a[4], const uint32_t b[2]) {
    asm volatile("mma.sync.aligned.m16n8k16.row.col.f32.f16.f16.f32 "
        "{%0,%1,%2,%3}, {%4,%5,%6,%7}, {%8,%9}, {%0,%1,%2,%3};"
        : "+f"(c[0]), "+f"(c[1]), "+f"(c[2]), "+f"(c[3])
        : "r"(a[0]), "r"(a[1]), "r"(a[2]), "r"(a[3]), "r"(b[0]), "r"(b[1]));
}
__device__ __forceinline__ void ldsm4(uint32_t r[4], uint32_t addr) {
    asm volatile("ldmatrix.sync.aligned.m8n8.x4.shared.b16 {%0,%1,%2,%3}, [%4];"
        : "=r"(r[0]), "=r"(r[1]), "=r"(r[2]), "=r"(r[3]) : "r"(addr));
}
__device__ __forceinline__ void ldsm4t(uint32_t r[4], uint32_t addr) {
    asm volatile("ldmatrix.sync.aligned.m8n8.x4.trans.shared.b16 {%0,%1,%2,%3}, [%4];"
        : "=r"(r[0]), "=r"(r[1]), "=r"(r[2]), "=r"(r[3]) : "r"(addr));
}
__device__ __forceinline__ void cp16(uint32_t saddr, const void* gaddr) {
    asm volatile("cp.async.cg.shared.global [%0], [%1], 16;" :: "r"(saddr), "l"(gaddr));
}
#define CP_COMMIT() asm volatile("cp.async.commit_group;")
template<int N> __device__ __forceinline__ void cp_wait() {
    asm volatile("cp.async.wait_group %0;" :: "n"(N));
}

// ---------------- prep: xconv (y=0) + 4x fold (y=1) in ONE launch ----------------
__global__ void prep_kernel(const float4* __restrict__ x,
                            const float* __restrict__ W0, const float* __restrict__ A0, const float* __restrict__ B0,
                            const float* __restrict__ W1, const float* __restrict__ A1, const float* __restrict__ B1,
                            const float* __restrict__ W2, const float* __restrict__ A2, const float* __restrict__ B2,
                            const float* __restrict__ W3, const float* __restrict__ A3, const float* __restrict__ B3) {
    if (blockIdx.y == 0) {
        // xconv: fp32 x -> fp16 (4096 blocks x 256 threads x 1 quad)
        int i = blockIdx.x * blockDim.x + threadIdx.x;
        float4 v = x[i];
        ((uint2*)g_xt)[i] = make_uint2(pkh2(v.x, v.y), pkh2(v.z, v.w));
    } else {
        // fold: Weff[z] = h(wscale * (W + 2 * B @ A)); 4 z's x 1024 blocks
        int b = blockIdx.x;
        int z = b >> 10;
        const float *W, *A, *B;
        if (z == 0) { W = W0; A = A0; B = B0; }
        else if (z == 1) { W = W1; A = A1; B = B1; }
        else if (z == 2) { W = W2; A = A2; B = B2; }
        else { W = W3; A = A3; B = B3; }
        float wscale = (z == 0) ? 0.125f * LOG2E : 1.0f;
        uint32_t* out = g_Weff[z];
        int idx = (b & 1023) * blockDim.x + threadIdx.x;   // quad index
        int o = idx >> 8;
        int i = (idx & 255) * 4;
        float4 w = *(const float4*)(W + o*EMBED + i);
        float s0 = 0.f, s1 = 0.f, s2 = 0.f, s3 = 0.f;
#pragma unroll
        for (int r = 0; r < RANK; r++) {
            float br = B[o*RANK + r];
            float4 a = *(const float4*)(A + r*EMBED + i);
            s0 = fmaf(br, a.x, s0); s1 = fmaf(br, a.y, s1);
            s2 = fmaf(br, a.z, s2); s3 = fmaf(br, a.w, s3);
        }
        uint2 u;
        u.x = pkh2(wscale * (w.x + LORA_SCALE * s0), wscale * (w.y + LORA_SCALE * s1));
        u.y = pkh2(wscale * (w.z + LORA_SCALE * s2), wscale * (w.w + LORA_SCALE * s3));
        *(uint2*)(out + idx*2) = u;
    }
}

// ---------------- fp16 GEMM: C[M,N] = A[M,K] @ Bw[N,K]^T + bias ----------------
// Round-15 proven config: CTA 64x128, 128 threads (4 warps, warp tile 32x64),
// k64 stages, 2-slot ring, 144B rows, 1 barrier per k64, 4 CTAs/SM.
#define GAST 9216            // A stage bytes (64 rows * 144B)
#define GSTAGE 27648         // A + B (128 rows * 144B)
#define GEMM_SMEM (2*GSTAGE) // 55296
template<int MODE>
__global__ __launch_bounds__(128, 4)
void gemm_tc(const __half* __restrict__ A, const __half* __restrict__ Wbase,
             const float* __restrict__ bz0, const float* __restrict__ bz1, const float* __restrict__ bz2,
             uint32_t* __restrict__ o0, uint32_t* __restrict__ o1, uint32_t* __restrict__ o2,
             float* __restrict__ ofp) {
    extern __shared__ char smg[];
    const int z = (MODE == 0) ? blockIdx.z : 0;
    const __half* Bw = Wbase + (size_t)z * (EMBED*EMBED);
    const float* bias = (z == 0) ? bz0 : (z == 1) ? bz1 : bz2;
    const float bscale = (MODE == 0 && z == 0) ? 0.125f * LOG2E : 1.0f;
    uint32_t* Ch = (z == 0) ? o0 : (z == 1) ? o1 : o2;

    const int tid = threadIdx.x, warp = tid >> 5, lane = tid & 31;
    const int g = lane >> 2, c = lane & 3;
    const int wm = (warp & 1) * 32, wn = (warp >> 1) * 64;
    const int m0 = blockIdx.y * 64, n0 = blockIdx.x * 128;

    const uint32_t sbase = (uint32_t)__cvta_generic_to_shared(smg);

    auto issue = [&](int s) {
        uint32_t off = sbase + (uint32_t)(s & 1) * GSTAGE;
#pragma unroll
        for (int p = 0; p < 4; p++) {
            int idx = tid + 128*p;
            int row = idx >> 3, part = idx & 7;
            cp16(off + row*144 + part*16,
                 A + (size_t)(m0 + row)*EMBED + s*64 + part*8);
        }
#pragma unroll
        for (int p = 0; p < 8; p++) {
            int idx = tid + 128*p;
            int row = idx >> 3, part = idx & 7;
            cp16(off + GAST + row*144 + part*16,
                 Bw + (size_t)(n0 + row)*EMBED + s*64 + part*8);
        }
    };

    float acc[2][8][4];
#pragma unroll
    for (int t = 0; t < 2; t++)
#pragma unroll
        for (int j = 0; j < 8; j++)
#pragma unroll
            for (int r = 0; r < 4; r++) acc[t][j][r] = 0.f;

    const int a_row  = lane & 15;
    const int a_half = (lane >> 4) * 16;
    const int b_row  = (lane & 7) + ((lane >> 4) << 3);
    const int b_half = ((lane >> 3) & 1) * 16;

    issue(0); CP_COMMIT();
    cp_wait<0>(); __syncthreads();

    for (int s = 0; s < EMBED/64; s++) {   // 16 iterations
        if (s + 1 < EMBED/64) { issue(s + 1); CP_COMMIT(); }

        uint32_t offA = sbase + (uint32_t)(s & 1) * GSTAGE;
        uint32_t offB = offA + GAST;

#pragma unroll
        for (int kk = 0; kk < 4; kk++) {
            uint32_t af[2][4], bf[8][2];
#pragma unroll
            for (int t = 0; t < 2; t++)
                ldsm4(af[t], offA + (uint32_t)(wm + 16*t + a_row)*144 + a_half + kk*32);
#pragma unroll
            for (int jj = 0; jj < 4; jj++) {
                uint32_t r[4];
                ldsm4(r, offB + (uint32_t)(wn + 16*jj + b_row)*144 + b_half + kk*32);
                bf[2*jj][0] = r[0]; bf[2*jj][1] = r[1];
                bf[2*jj+1][0] = r[2]; bf[2*jj+1][1] = r[3];
            }
#pragma unroll
            for (int t = 0; t < 2; t++)
#pragma unroll
                for (int j = 0; j < 8; j++)
                    mma_f16(acc[t][j], af[t], bf[j]);
        }

        cp_wait<0>();
        __syncthreads();
    }

    // epilogue
#pragma unroll
    for (int j = 0; j < 8; j++) {
        int col = n0 + wn + 8*j + 2*c;
        float bv0 = bias[col] * bscale, bv1 = bias[col + 1] * bscale;
#pragma unroll
        for (int t = 0; t < 2; t++) {
            int row0 = m0 + wm + 16*t + g;
            float v00 = acc[t][j][0] + bv0, v01 = acc[t][j][1] + bv1;
            float v10 = acc[t][j][2] + bv0, v11 = acc[t][j][3] + bv1;
            if (MODE == 1) {
                *(float2*)(ofp + (size_t)row0*EMBED + col)     = make_float2(v00, v01);
                *(float2*)(ofp + (size_t)(row0+8)*EMBED + col) = make_float2(v10, v11);
            } else {
                Ch[((size_t)row0*EMBED + col) >> 1]     = pkh2(v00, v01);
                Ch[((size_t)(row0+8)*EMBED + col) >> 1] = pkh2(v10, v11);
            }
        }
    }
}

// ---------------- flash attention: round-10 config (frozen) ----------------
#define KOB(s)  ((uint32_t)(s)*9216u)
#define VOB(s)  (18432u + (uint32_t)(s)*9216u)
#define QO      36864u
#define ATTN_SMEM (36864 + 9216)   // 46080
#define NT (SEQ/64)

__global__ __launch_bounds__(128, 4)
void attn_tc(const __half* __restrict__ Qg, const __half* __restrict__ Kg,
             const __half* __restrict__ Vg, uint32_t* __restrict__ Og) {
    extern __shared__ char sma[];
    const uint32_t sbase = (uint32_t)__cvta_generic_to_shared(sma);

    const int qt = blockIdx.x, h = blockIdx.y, nb = blockIdx.z;
    const int tid = threadIdx.x, warp = tid >> 5, lane = tid & 31;
    const int g = lane >> 2, c = lane & 3;
    const int q0 = warp * 16;
    const int base_q = nb*SEQ + qt*64;
    const int col0 = h * HDIM;

    auto kvissue = [&](int kt) {
        int s = kt & 1;
        int base_k = nb*SEQ + kt*64;
#pragma unroll
        for (int p = 0; p < 4; p++) {
            int idx = tid + 128*p;
            int row = idx >> 3, q = idx & 7;
            cp16(sbase + KOB(s) + row*144 + q*16,
                 Kg + (size_t)(base_k + row)*EMBED + col0 + 8*q);
        }
#pragma unroll
        for (int p = 0; p < 4; p++) {
            int idx = tid + 128*p;
            int row = idx >> 3, q = idx & 7;
            cp16(sbase + VOB(s) + row*144 + q*16,
                 Vg + (size_t)(base_k + row)*EMBED + col0 + 8*q);
        }
    };

#pragma unroll
    for (int p = 0; p < 4; p++) {
        int idx = tid + 128*p;
        int row = idx >> 3, q = idx & 7;
        cp16(sbase + QO + row*144 + q*16,
             Qg + (size_t)(base_q + row)*EMBED + col0 + 8*q);
    }
    CP_COMMIT();
    kvissue(0); CP_COMMIT();

    const int b_row  = (lane & 7) + ((lane >> 4) << 3);
    const int b_half = ((lane >> 3) & 1) * 16;
    const int v_row  = (lane & 7) + (((lane >> 3) & 1) << 3);
    const int v_half = (lane >> 4) * 16;

    cp_wait<0>(); __syncthreads();
    uint32_t qf[4][4];
#pragma unroll
    for (int kk = 0; kk < 4; kk++)
        ldsm4(qf[kk], sbase + QO + (uint32_t)(q0 + (lane & 15))*144 + (lane >> 4)*16 + kk*32);

    float of[8][4], of_l[4];
#pragma unroll
    for (int j = 0; j < 8; j++)
#pragma unroll
        for (int r = 0; r < 4; r++) of[j][r] = 0.f;
#pragma unroll
    for (int r = 0; r < 4; r++) of_l[r] = 0.f;
    float m_lo = -1e30f, m_hi = -1e30f;
    const uint32_t ones2 = 0x3C003C00u;

    for (int kt = 0; kt < NT; kt++) {
        if (kt + 1 < NT) { kvissue(kt + 1); CP_COMMIT(); }
        const uint32_t Ko = KOB(kt & 1);
        const uint32_t Vo = VOB(kt & 1);

        float sf[8][4];
#pragma unroll
        for (int j = 0; j < 8; j++)
#pragma unroll
            for (int r = 0; r < 4; r++) sf[j][r] = 0.f;
#pragma unroll
        for (int kk = 0; kk < 4; kk++) {
            uint32_t bf[8][2];
#pragma unroll
            for (int jj = 0; jj < 4; jj++) {
                uint32_t r[4];
                ldsm4(r, sbase + Ko + (uint32_t)(16*jj + b_row)*144 + b_half + kk*32);
                bf[2*jj][0] = r[0]; bf[2*jj][1] = r[1];
                bf[2*jj+1][0] = r[2]; bf[2*jj+1][1] = r[3];
            }
#pragma unroll
            for (int j = 0; j < 8; j++)
                mma_f16(sf[j], qf[kk], bf[j]);
        }

        float mx_lo = -1e30f, mx_hi = -1e30f;
#pragma unroll
        for (int j = 0; j < 8; j++) {
            mx_lo = fmaxf(mx_lo, fmaxf(sf[j][0], sf[j][1]));
            mx_hi = fmaxf(mx_hi, fmaxf(sf[j][2], sf[j][3]));
        }
        mx_lo = fmaxf(mx_lo, __shfl_xor_sync(0xffffffffu, mx_lo, 1));
        mx_lo = fmaxf(mx_lo, __shfl_xor_sync(0xffffffffu, mx_lo, 2));
        mx_hi = fmaxf(mx_hi, __shfl_xor_sync(0xffffffffu, mx_hi, 1));
        mx_hi = fmaxf(mx_hi, __shfl_xor_sync(0xffffffffu, mx_hi, 2));

        bool need_rescale = (mx_lo > m_lo) || (mx_hi > m_hi);
        float mn_lo = fmaxf(m_lo, mx_lo);
        float mn_hi = fmaxf(m_hi, mx_hi);

        if (need_rescale) {
            float alpha_lo = exp2f(m_lo - mn_lo);
            float alpha_hi = exp2f(m_hi - mn_hi);
#pragma unroll
            for (int j = 0; j < 8; j++) {
                of[j][0] *= alpha_lo; of[j][1] *= alpha_lo;
                of[j][2] *= alpha_hi; of[j][3] *= alpha_hi;
            }
            of_l[0] *= alpha_lo; of_l[1] *= alpha_lo;
            of_l[2] *= alpha_hi; of_l[3] *= alpha_hi;
            m_lo = mn_lo; m_hi = mn_hi;
        }

        __half2 ml2 = __float2half2_rn(mn_lo);
        __half2 mh2 = __float2half2_rn(mn_hi);
        uint32_t pa[4][4];
#pragma unroll
        for (int kk = 0; kk < 4; kk++) {
            pa[kk][0] = pexp2(sf[2*kk][0],   sf[2*kk][1],   ml2);
            pa[kk][1] = pexp2(sf[2*kk][2],   sf[2*kk][3],   mh2);
            pa[kk][2] = pexp2(sf[2*kk+1][0], sf[2*kk+1][1], ml2);
            pa[kk][3] = pexp2(sf[2*kk+1][2], sf[2*kk+1][3], mh2);
        }

#pragma unroll
        for (int kk = 0; kk < 4; kk++) {
#pragma unroll
            for (int dd = 0; dd < 4; dd++) {
                uint32_t r[4];
                ldsm4t(r, sbase + Vo + (uint32_t)(kk*16 + v_row)*144 + dd*32 + v_half);
                uint32_t b0[2] = { r[0], r[1] };
                uint32_t b1[2] = { r[2], r[3] };
                mma_f16(of[2*dd],   pa[kk], b0);
                mma_f16(of[2*dd+1], pa[kk], b1);
            }
            uint32_t ob[2] = { ones2, ones2 };
            mma_f16(of_l, pa[kk], ob);
        }

        cp_wait<0>();
        __syncthreads();
    }

    float il_lo = 1.f / of_l[0], il_hi = 1.f / of_l[2];
#pragma unroll
    for (int dj = 0; dj < 8; dj++) {
        int col = col0 + 8*dj + 2*c;
        Og[((size_t)(base_q + q0 + g)*EMBED + col) >> 1]     = pkh2(of[dj][0]*il_lo, of[dj][1]*il_lo);
        Og[((size_t)(base_q + q0 + g + 8)*EMBED + col) >> 1] = pkh2(of[dj][2]*il_hi, of[dj][3]*il_hi);
    }
}

// ---------------- launch ----------------
extern "C" void kernel_launch(void* const* d_in, const int* in_sizes, int n_in,
                              void* d_out, int out_size) {
    const float* x  = (const float*)d_in[0];
    const float* Wq = (const float*)d_in[1];
    const float* bq = (const float*)d_in[2];
    const float* Aq = (const float*)d_in[3];
    const float* Bq = (const float*)d_in[4];
    const float* Wk = (const float*)d_in[5];
    const float* bk = (const float*)d_in[6];
    const float* Ak = (const float*)d_in[7];
    const float* Bk = (const float*)d_in[8];
    const float* Wv = (const float*)d_in[9];
    const float* bv = (const float*)d_in[10];
    const float* Av = (const float*)d_in[11];
    const float* Bv = (const float*)d_in[12];
    const float* Wo = (const float*)d_in[13];
    const float* bo = (const float*)d_in[14];
    const float* Ao = (const float*)d_in[15];
    const float* Bo = (const float*)d_in[16];
    float* out = (float*)d_out;

    uint32_t *Weff, *xt, *Q, *K, *V, *attn;
    cudaGetSymbolAddress((void**)&Weff, g_Weff);
    cudaGetSymbolAddress((void**)&xt, g_xt);
    cudaGetSymbolAddress((void**)&Q, g_Q);
    cudaGetSymbolAddress((void**)&K, g_K);
    cudaGetSymbolAddress((void**)&V, g_V);
    cudaGetSymbolAddress((void**)&attn, g_attn);

    // 0+1) fused prep: x->fp16 conversion AND LoRA weight folding, one launch
    dim3 pgrid(TOKENS*EMBED/4/256, 2);
    prep_kernel<<<pgrid, 256>>>((const float4*)x,
                                Wq, Aq, Bq, Wk, Ak, Bk, Wv, Av, Bv, Wo, Ao, Bo);

    // 2) fused Q/K/V projections (64x128 tiles, k64 stages, 4 CTAs/SM)
    cudaFuncSetAttribute(gemm_tc<0>, cudaFuncAttributeMaxDynamicSharedMemorySize, GEMM_SMEM);
    cudaFuncSetAttribute(gemm_tc<1>, cudaFuncAttributeMaxDynamicSharedMemorySize, GEMM_SMEM);
    dim3 qkv_grid(EMBED/128, TOKENS/64, 3);
    gemm_tc<0><<<qkv_grid, 128, GEMM_SMEM>>>((const __half*)xt, (const __half*)Weff,
                                             bq, bk, bv, Q, K, V, nullptr);

    // 3) attention (frozen round-10 config)
    dim3 agrid(SEQ/64, HEADS, NBATCH);
    attn_tc<<<agrid, 128, ATTN_SMEM>>>((const __half*)Q, (const __half*)K, (const __half*)V, attn);

    // 4) output projection (fp32 out + bias; 512 CTAs = single wave at 4/SM)
    dim3 ogrid(EMBED/128, TOKENS/64, 1);
    gemm_tc<1><<<ogrid, 128, GEMM_SMEM>>>((const __half*)attn,
                                          (const __half*)(Weff + 3*(size_t)(EMBED*EMBED/2)),
                                          bo, bo, bo, nullptr, nullptr, nullptr, out);
}